// round 2
// baseline (speedup 1.0000x reference)
#include <cuda_runtime.h>

// ---------------------------------------------------------------------------
// SSIM fused kernel, f32x2-packed, for (16,3,512,512) fp32 pairs on sm_100a.
// ---------------------------------------------------------------------------

#define IMG_H 512
#define IMG_W 512
#define TW 64
#define TH 32
#define HALO 5
#define IW (TW + 10)          // 74
#define IH (TH + 10)          // 42
#define PITCH_I 76            // input smem pitch (floats, even for LDS.64)
#define PITCH_IU 38           // same in float2 units
#define NTHREADS 256

typedef unsigned long long ull;

// ---- compile-time Gaussian weights, double precision (match numpy) --------
constexpr double expser(double x) {
    double t = 1.0, s = 1.0;
    for (int k = 1; k < 100; k++) { t = t * x / (double)k; s += t; }
    return s;
}
constexpr double gk(int i) { double d = (double)(i - 5); return 1.0 / expser(d * d / 4.5); }
constexpr double GSUM = gk(0)+gk(1)+gk(2)+gk(3)+gk(4)+gk(5)+gk(6)+gk(7)+gk(8)+gk(9)+gk(10);
constexpr float WF(int i) { return (float)(gk(i) / GSUM); }
__device__ constexpr float W[11] = {WF(0),WF(1),WF(2),WF(3),WF(4),WF(5),
                                    WF(6),WF(7),WF(8),WF(9),WF(10)};

// ---- f32x2 packed helpers -------------------------------------------------
__device__ __forceinline__ ull fma2(ull a, ull b, ull c) {
    ull d;
    asm("fma.rn.f32x2 %0, %1, %2, %3;" : "=l"(d) : "l"(a), "l"(b), "l"(c));
    return d;
}
__device__ __forceinline__ ull mul2(ull a, ull b) {   // rn(a*b) via fma with 0
    ull d;
    asm("fma.rn.f32x2 %0, %1, %2, %3;" : "=l"(d) : "l"(a), "l"(b), "l"(0ULL));
    return d;
}
__device__ __forceinline__ ull bc2(float w) {
    ull u;
    asm("mov.b64 %0, {%1, %1};" : "=l"(u) : "f"(w));
    return u;
}
__device__ __forceinline__ ull pk2(float x, float y) {
    ull u;
    asm("mov.b64 %0, {%1, %2};" : "=l"(u) : "f"(x), "f"(y));
    return u;
}
__device__ __forceinline__ float lo2(ull u) {
    float x; asm("{ .reg .f32 hi; mov.b64 {%0, hi}, %1; }" : "=f"(x) : "l"(u));
    return x;
}
__device__ __forceinline__ float hi2(ull u) {
    float y; asm("{ .reg .f32 lo; mov.b64 {lo, %0}, %1; }" : "=f"(y) : "l"(u));
    return y;
}
__device__ __forceinline__ ull neg2(ull a) { return a ^ 0x8000000080000000ULL; }
__device__ __forceinline__ ull add2(ull a, ull b) { return fma2(bc2(1.0f), a, b); }

__device__ double g_sum;
__device__ unsigned g_cnt;

__global__ __launch_bounds__(NTHREADS, 2)
void ssim_main(const float* __restrict__ img1, const float* __restrict__ img2,
               float* __restrict__ out, double inv_n, unsigned nblocks) {
    extern __shared__ float sm[];
    float* sI1 = sm;                              // IH * PITCH_I
    float* sI2 = sm + IH * PITCH_I;               // IH * PITCH_I
    ull*   sT  = (ull*)(sm + 2 * IH * PITCH_I);   // 5 * IW * 16 float2 (swizzled, transposed)
    __shared__ double sRed[4];

    const int tid = threadIdx.x;
    const int plane = blockIdx.z;
    const int ty0 = blockIdx.y * TH;
    const int tx0 = blockIdx.x * TW;
    const float* p1 = img1 + (size_t)plane * (IMG_H * IMG_W);
    const float* p2 = img2 + (size_t)plane * (IMG_H * IMG_W);

    // -------- phase 1: load halo'd tile of both images (zero-pad OOB) ------
    for (int i = tid; i < IH * IW; i += NTHREADS) {
        int ly = i / IW;
        int lx = i - ly * IW;
        int gy = ty0 - HALO + ly;
        int gx = tx0 - HALO + lx;
        float a = 0.0f, b = 0.0f;
        if ((unsigned)gy < (unsigned)IMG_H && (unsigned)gx < (unsigned)IMG_W) {
            int g = gy * IMG_W + gx;
            a = p1[g];
            b = p2[g];
        }
        sI1[ly * PITCH_I + lx] = a;
        sI2[ly * PITCH_I + lx] = b;
    }
    __syncthreads();

    // -------- phase 2: vertical conv of 5 quantities, packed over x --------
    // task = (xpair 0..36, strip s 0..7 of 4 rows). 296 tasks.
    {
        const ull* u1 = (const ull*)sI1;
        const ull* u2 = (const ull*)sI2;
        for (int t = tid; t < 37 * 8; t += NTHREADS) {
            int xh = t % 37;
            int s  = t / 37;
            ull acc[5][4];
#pragma unroll
            for (int q = 0; q < 5; q++)
#pragma unroll
                for (int k = 0; k < 4; k++) acc[q][k] = 0ULL;

#pragma unroll
            for (int j = 0; j < 14; j++) {
                ull a  = u1[(4 * s + j) * PITCH_IU + xh];
                ull b  = u2[(4 * s + j) * PITCH_IU + xh];
                ull aa = mul2(a, a);
                ull bb = mul2(b, b);
                ull ab = mul2(a, b);
#pragma unroll
                for (int k = 0; k < 4; k++) {
                    if ((unsigned)(j - k) < 11u) {
                        ull wp = bc2(W[j - k]);
                        acc[0][k] = fma2(wp, a,  acc[0][k]);
                        acc[1][k] = fma2(wp, b,  acc[1][k]);
                        acc[2][k] = fma2(wp, aa, acc[2][k]);
                        acc[3][k] = fma2(wp, bb, acc[3][k]);
                        acc[4][k] = fma2(wp, ab, acc[4][k]);
                    }
                }
            }
            // store transposed, y-paired, swizzled: column x, pair-index k^ = row>>1
#pragma unroll
            for (int q = 0; q < 5; q++) {
#pragma unroll
                for (int r = 0; r < 2; r++) {
                    int kh = 2 * s + r;
                    int sw = (kh + xh) & 15;
                    sT[(q * IW + 2 * xh)     * 16 + sw] = pk2(lo2(acc[q][2*r]), lo2(acc[q][2*r+1]));
                    sT[(q * IW + 2 * xh + 1) * 16 + sw] = pk2(hi2(acc[q][2*r]), hi2(acc[q][2*r+1]));
                }
            }
        }
    }
    __syncthreads();

    // -------- phase 3: horizontal conv packed over y-pairs + SSIM ----------
    float local = 0.0f;
    if (tid < 128) {
        const int p  = tid & 15;        // y-pair: rows 2p, 2p+1
        const int b  = tid >> 4;        // x-block of 8: cols 8b..8b+7
        const int x0 = 8 * b;

        ull m[5][8];
#pragma unroll
        for (int q = 0; q < 5; q++)
#pragma unroll
            for (int o = 0; o < 8; o++) m[q][o] = 0ULL;

#pragma unroll
        for (int q = 0; q < 5; q++) {
#pragma unroll
            for (int j = 0; j < 18; j++) {
                int x = x0 + j;
                ull A = sT[(q * IW + x) * 16 + ((p + (x >> 1)) & 15)];
#pragma unroll
                for (int o = 0; o < 8; o++) {
                    if ((unsigned)(j - o) < 11u)
                        m[q][o] = fma2(bc2(W[j - o]), A, m[q][o]);
                }
            }
        }

        const ull C1p  = bc2(1e-4f);
        const ull C2p  = bc2(9e-4f);
        const ull TWOp = bc2(2.0f);
#pragma unroll
        for (int o = 0; o < 8; o++) {
            ull m1 = m[0][o], m2 = m[1][o];
            ull m1s = mul2(m1, m1);
            ull m2s = mul2(m2, m2);
            ull m12 = mul2(m1, m2);
            ull nm1 = neg2(m1);
            ull s1  = fma2(nm1, m1, m[2][o]);      // E[x^2] - mu1^2
            ull s2  = fma2(neg2(m2), m2, m[3][o]); // E[y^2] - mu2^2
            ull s12 = fma2(nm1, m2, m[4][o]);      // E[xy] - mu1*mu2
            ull numA = fma2(TWOp, m12, C1p);
            ull numB = fma2(TWOp, s12, C2p);
            ull denA = add2(m1s, add2(m2s, C1p));
            ull denB = add2(s1,  add2(s2,  C2p));
            ull num  = mul2(numA, numB);
            ull den  = mul2(denA, denB);
            local += __fdividef(lo2(num), lo2(den));
            local += __fdividef(hi2(num), hi2(den));
        }

        unsigned mask = 0xffffffffu;
#pragma unroll
        for (int s = 16; s > 0; s >>= 1) local += __shfl_down_sync(mask, local, s);
        if ((tid & 31) == 0) sRed[tid >> 5] = (double)local;
    }
    __syncthreads();

    if (tid == 0) {
        double s = sRed[0] + sRed[1] + sRed[2] + sRed[3];
        atomicAdd(&g_sum, s);
        __threadfence();
        unsigned done = atomicAdd(&g_cnt, 1);
        if (done == nblocks - 1) {
            double v = *((volatile double*)&g_sum);
            out[0] = (float)(v * inv_n);
            g_sum = 0.0;
            g_cnt = 0;
            __threadfence();
        }
    }
}

// ---------------------------------------------------------------------------

extern "C" void kernel_launch(void* const* d_in, const int* in_sizes, int n_in,
                              void* d_out, int out_size) {
    const float* img1 = (const float*)d_in[0];
    const float* img2 = (const float*)d_in[1];
    float* out = (float*)d_out;

    const int total  = in_sizes[0];                 // 16*3*512*512
    const int planes = total / (IMG_H * IMG_W);     // 48

    const int smem_bytes = 2 * IH * PITCH_I * (int)sizeof(float)
                         + 5 * IW * 16 * (int)sizeof(ull);   // 25536 + 47360 = 72896

    static bool attr_set = false;
    if (!attr_set) {
        cudaFuncSetAttribute(ssim_main, cudaFuncAttributeMaxDynamicSharedMemorySize,
                             smem_bytes);
        attr_set = true;
    }

    dim3 grid(IMG_W / TW, IMG_H / TH, planes);      // 8 x 16 x 48 = 6144
    unsigned nblocks = grid.x * grid.y * grid.z;
    ssim_main<<<grid, NTHREADS, smem_bytes>>>(img1, img2, out,
                                              1.0 / (double)total, nblocks);
}

// round 3
// speedup vs baseline: 1.3336x; 1.3336x over previous
#include <cuda_runtime.h>

// ---------------------------------------------------------------------------
// SSIM fused kernel, f32x2-packed, occupancy/balance-tuned, sm_100a.
// (16,3,512,512) fp32 pairs -> mean SSIM.
// ---------------------------------------------------------------------------

#define IMG_H 512
#define IMG_W 512
#define TW 64
#define TH 32
#define HALO 5
#define IW 74
#define IH 42
#define PITCH_I 76            // input smem pitch (floats)
#define PITCH_IU 38           // input smem pitch (float2)
#define CS_PITCH 37           // colsum pitch in float2 (odd -> conflict-free)
#define NTHREADS 256

typedef unsigned long long ull;

// ---- compile-time Gaussian weights, double precision (match numpy) --------
constexpr double expser(double x) {
    double t = 1.0, s = 1.0;
    for (int k = 1; k < 100; k++) { t = t * x / (double)k; s += t; }
    return s;
}
constexpr double gk(int i) { double d = (double)(i - 5); return 1.0 / expser(d * d / 4.5); }
constexpr double GSUM = gk(0)+gk(1)+gk(2)+gk(3)+gk(4)+gk(5)+gk(6)+gk(7)+gk(8)+gk(9)+gk(10);
constexpr float WF(int i) { return (float)(gk(i) / GSUM); }
__device__ constexpr float W[11] = {WF(0),WF(1),WF(2),WF(3),WF(4),WF(5),
                                    WF(6),WF(7),WF(8),WF(9),WF(10)};

// ---- f32x2 packed helpers -------------------------------------------------
__device__ __forceinline__ ull fma2(ull a, ull b, ull c) {
    ull d;
    asm("fma.rn.f32x2 %0, %1, %2, %3;" : "=l"(d) : "l"(a), "l"(b), "l"(c));
    return d;
}
__device__ __forceinline__ ull mul2(ull a, ull b) {
    ull d;
    asm("fma.rn.f32x2 %0, %1, %2, %3;" : "=l"(d) : "l"(a), "l"(b), "l"(0ULL));
    return d;
}
__device__ __forceinline__ ull bc2(float w) {
    ull u;
    asm("mov.b64 %0, {%1, %1};" : "=l"(u) : "f"(w));
    return u;
}
__device__ __forceinline__ ull pk2(float x, float y) {
    ull u;
    asm("mov.b64 %0, {%1, %2};" : "=l"(u) : "f"(x), "f"(y));
    return u;
}
__device__ __forceinline__ float lo2(ull u) {
    float x; asm("{ .reg .f32 hi; mov.b64 {%0, hi}, %1; }" : "=f"(x) : "l"(u));
    return x;
}
__device__ __forceinline__ float hi2(ull u) {
    float y; asm("{ .reg .f32 lo; mov.b64 {lo, %0}, %1; }" : "=f"(y) : "l"(u));
    return y;
}
__device__ __forceinline__ ull neg2(ull a) { return a ^ 0x8000000080000000ULL; }
__device__ __forceinline__ ull add2(ull a, ull b) { return fma2(bc2(1.0f), a, b); }

__device__ double g_sum;
__device__ unsigned g_cnt;

// vertical packed conv, one quantity, 8-row strip, one x-pair column
template <int Q>
__device__ __forceinline__ void vpass2(const ull* __restrict__ a,
                                       const ull* __restrict__ b,
                                       ull* __restrict__ dst,
                                       const ull* __restrict__ Wp) {
    ull acc[8];
#pragma unroll
    for (int k = 0; k < 8; k++) acc[k] = 0ULL;
#pragma unroll
    for (int j = 0; j < 18; j++) {
        ull v;
        if (Q == 0)      { v = a[j * PITCH_IU]; }
        else if (Q == 1) { v = b[j * PITCH_IU]; }
        else if (Q == 2) { ull t = a[j * PITCH_IU]; v = mul2(t, t); }
        else if (Q == 3) { ull t = b[j * PITCH_IU]; v = mul2(t, t); }
        else             { v = mul2(a[j * PITCH_IU], b[j * PITCH_IU]); }
#pragma unroll
        for (int k = 0; k < 8; k++)
            if ((unsigned)(j - k) < 11u)
                acc[k] = fma2(Wp[j - k], v, acc[k]);
    }
#pragma unroll
    for (int k = 0; k < 8; k++) dst[k * CS_PITCH] = acc[k];
}

__global__ __launch_bounds__(NTHREADS, 3)
void ssim_main(const float* __restrict__ img1, const float* __restrict__ img2,
               float* __restrict__ out, double inv_n, unsigned nblocks) {
    extern __shared__ float sm[];
    float* sI1 = sm;                               // IH * PITCH_I
    float* sI2 = sm + IH * PITCH_I;                // IH * PITCH_I
    ull*   sCS = (ull*)(sm + 2 * IH * PITCH_I);    // 5 * TH * CS_PITCH float2
    __shared__ double sRed[NTHREADS / 32];

    const int tid = threadIdx.x;
    const int plane = blockIdx.z;
    const int ty0 = blockIdx.y * TH;
    const int tx0 = blockIdx.x * TW;
    const float* p1 = img1 + (size_t)plane * (IMG_H * IMG_W);
    const float* p2 = img2 + (size_t)plane * (IMG_H * IMG_W);

    ull Wp[11];
#pragma unroll
    for (int w = 0; w < 11; w++) Wp[w] = bc2(W[w]);

    // -------- phase 1: load halo'd tile of both images (zero-pad OOB) ------
    for (int i = tid; i < IH * IW; i += NTHREADS) {
        int ly = i / IW;
        int lx = i - ly * IW;
        int gy = ty0 - HALO + ly;
        int gx = tx0 - HALO + lx;
        float a = 0.0f, b = 0.0f;
        if ((unsigned)gy < (unsigned)IMG_H && (unsigned)gx < (unsigned)IMG_W) {
            int g = gy * IMG_W + gx;
            a = p1[g];
            b = p2[g];
        }
        sI1[ly * PITCH_I + lx] = a;
        sI2[ly * PITCH_I + lx] = b;
    }
    __syncthreads();

    // -------- phase 2: vertical conv of 5 quantities, packed over x --------
    // 800 padded slots: xh in [0,40) (valid < 37), strip in [0,4), q in [0,5).
    // q boundary = every 160 slots = 32-aligned -> warp-uniform template.
    {
        const ull* u1 = (const ull*)sI1;
        const ull* u2 = (const ull*)sI2;
        for (int t = tid; t < 800; t += NTHREADS) {
            int xh = t % 40;
            int r  = t / 40;            // 0..19
            int s  = r & 3;
            int q  = r >> 2;
            if (xh < CS_PITCH) {
                const ull* a = u1 + (8 * s) * PITCH_IU + xh;
                const ull* b = u2 + (8 * s) * PITCH_IU + xh;
                ull* dst = sCS + (q * TH + 8 * s) * CS_PITCH + xh;
                switch (q) {
                    case 0: vpass2<0>(a, b, dst, Wp); break;
                    case 1: vpass2<1>(a, b, dst, Wp); break;
                    case 2: vpass2<2>(a, b, dst, Wp); break;
                    case 3: vpass2<3>(a, b, dst, Wp); break;
                    default: vpass2<4>(a, b, dst, Wp); break;
                }
            }
        }
    }
    __syncthreads();

    // -------- phase 3: horizontal conv packed over x-pairs + SSIM ----------
    // thread (y = tid&31, xb = tid>>5): 4 output packs = 8 pixels.
    float local = 0.0f;
    {
        const int y  = tid & 31;
        const int xb = tid >> 5;

        ull m[5][4];
#pragma unroll
        for (int q = 0; q < 5; q++)
#pragma unroll
            for (int o = 0; o < 4; o++) m[q][o] = 0ULL;

#pragma unroll
        for (int q = 0; q < 5; q++) {
            const ull* cs = sCS + (q * TH + y) * CS_PITCH + 4 * xb;
            ull Pp = cs[0];
            m[q][0] = fma2(Wp[0], Pp, m[q][0]);          // e=0 aligned, o=0
#pragma unroll
            for (int i = 1; i < 9; i++) {
                ull Pi = cs[i];
                ull Se = pk2(hi2(Pp), lo2(Pi));          // shifted pair e=i-1
#pragma unroll
                for (int o = 0; o < 4; o++) {
                    int d = (i - 1) - o;                 // shifted tap 2d+1
                    if (d >= 0 && d <= 4)
                        m[q][o] = fma2(Wp[2 * d + 1], Se, m[q][o]);
                    int e = i - o;                       // aligned tap 2e
                    if (e >= 0 && e <= 5)
                        m[q][o] = fma2(Wp[2 * e], Pi, m[q][o]);
                }
                Pp = Pi;
            }
        }

        const ull C1p  = bc2(1e-4f);
        const ull C2p  = bc2(9e-4f);
        const ull TWOp = bc2(2.0f);
#pragma unroll
        for (int o = 0; o < 4; o++) {
            ull m1 = m[0][o], m2 = m[1][o];
            ull m1s = mul2(m1, m1);
            ull m2s = mul2(m2, m2);
            ull m12 = mul2(m1, m2);
            ull nm1 = neg2(m1);
            ull s1  = fma2(nm1, m1, m[2][o]);
            ull s2  = fma2(neg2(m2), m2, m[3][o]);
            ull s12 = fma2(nm1, m2, m[4][o]);
            ull numA = fma2(TWOp, m12, C1p);
            ull numB = fma2(TWOp, s12, C2p);
            ull denA = add2(m1s, add2(m2s, C1p));
            ull denB = add2(s1,  add2(s2,  C2p));
            ull num  = mul2(numA, numB);
            ull den  = mul2(denA, denB);
            local += __fdividef(lo2(num), lo2(den));
            local += __fdividef(hi2(num), hi2(den));
        }

        unsigned mask = 0xffffffffu;
#pragma unroll
        for (int s = 16; s > 0; s >>= 1) local += __shfl_down_sync(mask, local, s);
        if ((tid & 31) == 0) sRed[tid >> 5] = (double)local;
    }
    __syncthreads();

    if (tid == 0) {
        double s = 0.0;
#pragma unroll
        for (int w = 0; w < NTHREADS / 32; w++) s += sRed[w];
        atomicAdd(&g_sum, s);
        __threadfence();
        unsigned done = atomicAdd(&g_cnt, 1);
        if (done == nblocks - 1) {
            double v = *((volatile double*)&g_sum);
            out[0] = (float)(v * inv_n);
            g_sum = 0.0;
            g_cnt = 0;
            __threadfence();
        }
    }
}

// ---------------------------------------------------------------------------

extern "C" void kernel_launch(void* const* d_in, const int* in_sizes, int n_in,
                              void* d_out, int out_size) {
    const float* img1 = (const float*)d_in[0];
    const float* img2 = (const float*)d_in[1];
    float* out = (float*)d_out;

    const int total  = in_sizes[0];                 // 16*3*512*512
    const int planes = total / (IMG_H * IMG_W);     // 48

    const int smem_bytes = 2 * IH * PITCH_I * (int)sizeof(float)
                         + 5 * TH * CS_PITCH * (int)sizeof(ull);  // 25536+47360=72896

    static bool attr_set = false;
    if (!attr_set) {
        cudaFuncSetAttribute(ssim_main, cudaFuncAttributeMaxDynamicSharedMemorySize,
                             smem_bytes);
        attr_set = true;
    }

    dim3 grid(IMG_W / TW, IMG_H / TH, planes);      // 8 x 16 x 48 = 6144
    unsigned nblocks = grid.x * grid.y * grid.z;
    ssim_main<<<grid, NTHREADS, smem_bytes>>>(img1, img2, out,
                                              1.0 / (double)total, nblocks);
}

// round 4
// speedup vs baseline: 1.4102x; 1.0574x over previous
#include <cuda_runtime.h>

// ---------------------------------------------------------------------------
// SSIM fused kernel, f32x2-packed, TH=16 high-occupancy variant, sm_100a.
// (16,3,512,512) fp32 pairs -> mean SSIM.
// ---------------------------------------------------------------------------

#define IMG_H 512
#define IMG_W 512
#define TW 64
#define TH 16
#define HALO 5
#define IW 74                 // TW + 10
#define IH 26                 // TH + 10
#define PITCH_I 76            // input smem pitch (floats)
#define PITCH_IU 38           // input smem pitch (float2)
#define CS_PITCH 37           // colsum pitch (float2), odd
#define NTHREADS 256

typedef unsigned long long ull;

// ---- compile-time Gaussian weights, double precision (match numpy) --------
constexpr double expser(double x) {
    double t = 1.0, s = 1.0;
    for (int k = 1; k < 100; k++) { t = t * x / (double)k; s += t; }
    return s;
}
constexpr double gk(int i) { double d = (double)(i - 5); return 1.0 / expser(d * d / 4.5); }
constexpr double GSUM = gk(0)+gk(1)+gk(2)+gk(3)+gk(4)+gk(5)+gk(6)+gk(7)+gk(8)+gk(9)+gk(10);
constexpr float WF(int i) { return (float)(gk(i) / GSUM); }
__device__ constexpr float W[11] = {WF(0),WF(1),WF(2),WF(3),WF(4),WF(5),
                                    WF(6),WF(7),WF(8),WF(9),WF(10)};

// ---- f32x2 packed helpers -------------------------------------------------
__device__ __forceinline__ ull fma2(ull a, ull b, ull c) {
    ull d;
    asm("fma.rn.f32x2 %0, %1, %2, %3;" : "=l"(d) : "l"(a), "l"(b), "l"(c));
    return d;
}
__device__ __forceinline__ ull mul2(ull a, ull b) {
    ull d;
    asm("fma.rn.f32x2 %0, %1, %2, %3;" : "=l"(d) : "l"(a), "l"(b), "l"(0ULL));
    return d;
}
__device__ __forceinline__ ull bc2(float w) {
    ull u;
    asm("mov.b64 %0, {%1, %1};" : "=l"(u) : "f"(w));
    return u;
}
__device__ __forceinline__ ull pk2(float x, float y) {
    ull u;
    asm("mov.b64 %0, {%1, %2};" : "=l"(u) : "f"(x), "f"(y));
    return u;
}
__device__ __forceinline__ float lo2(ull u) {
    float x; asm("{ .reg .f32 hi; mov.b64 {%0, hi}, %1; }" : "=f"(x) : "l"(u));
    return x;
}
__device__ __forceinline__ float hi2(ull u) {
    float y; asm("{ .reg .f32 lo; mov.b64 {lo, %0}, %1; }" : "=f"(y) : "l"(u));
    return y;
}
__device__ __forceinline__ ull neg2(ull a) { return a ^ 0x8000000080000000ULL; }
__device__ __forceinline__ ull add2(ull a, ull b) { return fma2(bc2(1.0f), a, b); }

__device__ double g_sum;
__device__ unsigned g_cnt;

__global__ __launch_bounds__(NTHREADS, 4)
void ssim_main(const float* __restrict__ img1, const float* __restrict__ img2,
               float* __restrict__ out, double inv_n, unsigned nblocks) {
    extern __shared__ float sm[];
    float* sI1 = sm;                               // IH * PITCH_I floats
    float* sI2 = sm + IH * PITCH_I;
    ull*   sCS = (ull*)(sm + 2 * IH * PITCH_I);    // 5 * TH * CS_PITCH float2
    __shared__ double sRed[NTHREADS / 32];

    const int tid = threadIdx.x;
    const int plane = blockIdx.z;
    const int ty0 = blockIdx.y * TH;
    const int tx0 = blockIdx.x * TW;
    const float* p1 = img1 + (size_t)plane * (IMG_H * IMG_W);
    const float* p2 = img2 + (size_t)plane * (IMG_H * IMG_W);

    // -------- phase 1: load halo'd tile of both images (zero-pad OOB) ------
    for (int i = tid; i < IH * IW; i += NTHREADS) {
        int ly = i / IW;
        int lx = i - ly * IW;
        int gy = ty0 - HALO + ly;
        int gx = tx0 - HALO + lx;
        float a = 0.0f, b = 0.0f;
        if ((unsigned)gy < (unsigned)IMG_H && (unsigned)gx < (unsigned)IMG_W) {
            int g = gy * IMG_W + gx;
            a = p1[g];
            b = p2[g];
        }
        sI1[ly * PITCH_I + lx] = a;
        sI2[ly * PITCH_I + lx] = b;
    }
    __syncthreads();

    // -------- phase 2: vertical conv, all 5 quantities per task ------------
    // task = (xh in [0,37), strip s in [0,4) of 4 output rows).
    // 148 tasks, mapped t = tid < 160 (xh = t%40 padded). Single wave.
    {
        const ull* u1 = (const ull*)sI1;
        const ull* u2 = (const ull*)sI2;
        const int t = tid;
        if (t < 160) {
            const int xh = t % 40;
            const int s  = t / 40;
            if (xh < CS_PITCH) {
                const ull* pa = u1 + (4 * s) * PITCH_IU + xh;
                const ull* pb = u2 + (4 * s) * PITCH_IU + xh;
                ull acc[5][4];
#pragma unroll
                for (int q = 0; q < 5; q++)
#pragma unroll
                    for (int k = 0; k < 4; k++) acc[q][k] = 0ULL;

#pragma unroll
                for (int j = 0; j < 14; j++) {
                    ull a  = pa[j * PITCH_IU];
                    ull b  = pb[j * PITCH_IU];
                    ull aa = mul2(a, a);
                    ull bb = mul2(b, b);
                    ull ab = mul2(a, b);
#pragma unroll
                    for (int k = 0; k < 4; k++) {
                        if ((unsigned)(j - k) < 11u) {
                            ull wp = bc2(W[j - k]);
                            acc[0][k] = fma2(wp, a,  acc[0][k]);
                            acc[1][k] = fma2(wp, b,  acc[1][k]);
                            acc[2][k] = fma2(wp, aa, acc[2][k]);
                            acc[3][k] = fma2(wp, bb, acc[3][k]);
                            acc[4][k] = fma2(wp, ab, acc[4][k]);
                        }
                    }
                }
#pragma unroll
                for (int q = 0; q < 5; q++)
#pragma unroll
                    for (int k = 0; k < 4; k++)
                        sCS[(q * TH + 4 * s + k) * CS_PITCH + xh] = acc[q][k];
            }
        }
    }
    __syncthreads();

    // -------- phase 3: horizontal conv packed over x-pairs + SSIM ----------
    // 128 active threads: y = tid&15, xb = tid>>4 in [0,8): 4 packs = 8 px.
    float local = 0.0f;
    if (tid < 128) {
        const int y  = tid & 15;
        const int xb = tid >> 4;

        ull m[5][4];
#pragma unroll
        for (int q = 0; q < 5; q++)
#pragma unroll
            for (int o = 0; o < 4; o++) m[q][o] = 0ULL;

#pragma unroll
        for (int q = 0; q < 5; q++) {
            const ull* cs = sCS + (q * TH + y) * CS_PITCH + 4 * xb;
            ull Pp = cs[0];
            m[q][0] = fma2(bc2(W[0]), Pp, m[q][0]);      // e=0 aligned, o=0
#pragma unroll
            for (int i = 1; i < 9; i++) {
                ull Pi = cs[i];
                ull Se = pk2(hi2(Pp), lo2(Pi));          // shifted pair e=i-1
#pragma unroll
                for (int o = 0; o < 4; o++) {
                    int d = (i - 1) - o;                 // shifted tap 2d+1
                    if (d >= 0 && d <= 4)
                        m[q][o] = fma2(bc2(W[2 * d + 1]), Se, m[q][o]);
                    int e = i - o;                       // aligned tap 2e
                    if (e >= 0 && e <= 5)
                        m[q][o] = fma2(bc2(W[2 * e]), Pi, m[q][o]);
                }
                Pp = Pi;
            }
        }

        const ull C1p  = bc2(1e-4f);
        const ull C2p  = bc2(9e-4f);
        const ull TWOp = bc2(2.0f);
#pragma unroll
        for (int o = 0; o < 4; o++) {
            ull m1 = m[0][o], m2 = m[1][o];
            ull m1s = mul2(m1, m1);
            ull m2s = mul2(m2, m2);
            ull m12 = mul2(m1, m2);
            ull nm1 = neg2(m1);
            ull s1  = fma2(nm1, m1, m[2][o]);
            ull s2  = fma2(neg2(m2), m2, m[3][o]);
            ull s12 = fma2(nm1, m2, m[4][o]);
            ull numA = fma2(TWOp, m12, C1p);
            ull numB = fma2(TWOp, s12, C2p);
            ull denA = add2(m1s, add2(m2s, C1p));
            ull denB = add2(s1,  add2(s2,  C2p));
            ull num  = mul2(numA, numB);
            ull den  = mul2(denA, denB);
            local += __fdividef(lo2(num), lo2(den));
            local += __fdividef(hi2(num), hi2(den));
        }
    }

    // -------- reduction ----------------------------------------------------
    {
        unsigned mask = 0xffffffffu;
#pragma unroll
        for (int s = 16; s > 0; s >>= 1) local += __shfl_down_sync(mask, local, s);
        if ((tid & 31) == 0) sRed[tid >> 5] = (double)local;
    }
    __syncthreads();

    if (tid == 0) {
        double s = 0.0;
#pragma unroll
        for (int w = 0; w < NTHREADS / 32; w++) s += sRed[w];
        atomicAdd(&g_sum, s);
        __threadfence();
        unsigned done = atomicAdd(&g_cnt, 1);
        if (done == nblocks - 1) {
            double v = *((volatile double*)&g_sum);
            out[0] = (float)(v * inv_n);
            g_sum = 0.0;
            g_cnt = 0;
            __threadfence();
        }
    }
}

// ---------------------------------------------------------------------------

extern "C" void kernel_launch(void* const* d_in, const int* in_sizes, int n_in,
                              void* d_out, int out_size) {
    const float* img1 = (const float*)d_in[0];
    const float* img2 = (const float*)d_in[1];
    float* out = (float*)d_out;

    const int total  = in_sizes[0];                 // 16*3*512*512
    const int planes = total / (IMG_H * IMG_W);     // 48

    const int smem_bytes = 2 * IH * PITCH_I * (int)sizeof(float)
                         + 5 * TH * CS_PITCH * (int)sizeof(ull);  // 15808+23680=39488

    static bool attr_set = false;
    if (!attr_set) {
        cudaFuncSetAttribute(ssim_main, cudaFuncAttributeMaxDynamicSharedMemorySize,
                             smem_bytes);
        attr_set = true;
    }

    dim3 grid(IMG_W / TW, IMG_H / TH, planes);      // 8 x 32 x 48 = 12288
    unsigned nblocks = grid.x * grid.y * grid.z;
    ssim_main<<<grid, NTHREADS, smem_bytes>>>(img1, img2, out,
                                              1.0 / (double)total, nblocks);
}

// round 5
// speedup vs baseline: 1.5691x; 1.1127x over previous
#include <cuda_runtime.h>

// ---------------------------------------------------------------------------
// SSIM fused kernel, f32x2-packed, 160-thread balanced-phase variant, sm_100a.
// (16,3,512,512) fp32 pairs -> mean SSIM.
// ---------------------------------------------------------------------------

#define IMG_H 512
#define IMG_W 512
#define TW 64
#define TH 16
#define HALO 5
#define IW 74                 // TW + 10
#define IH 26                 // TH + 10
#define PITCH_I 76            // input smem pitch (floats)
#define PITCH_IU 38           // input smem pitch (float2)
#define CS_PITCH 37           // colsum pitch (float2), odd
#define NTHREADS 160
#define NWARPS 5

typedef unsigned long long ull;

// ---- compile-time Gaussian weights, double precision (match numpy) --------
constexpr double expser(double x) {
    double t = 1.0, s = 1.0;
    for (int k = 1; k < 100; k++) { t = t * x / (double)k; s += t; }
    return s;
}
constexpr double gk(int i) { double d = (double)(i - 5); return 1.0 / expser(d * d / 4.5); }
constexpr double GSUM = gk(0)+gk(1)+gk(2)+gk(3)+gk(4)+gk(5)+gk(6)+gk(7)+gk(8)+gk(9)+gk(10);
constexpr float WF(int i) { return (float)(gk(i) / GSUM); }
__device__ constexpr float W[11] = {WF(0),WF(1),WF(2),WF(3),WF(4),WF(5),
                                    WF(6),WF(7),WF(8),WF(9),WF(10)};

// ---- f32x2 packed helpers -------------------------------------------------
__device__ __forceinline__ ull fma2(ull a, ull b, ull c) {
    ull d;
    asm("fma.rn.f32x2 %0, %1, %2, %3;" : "=l"(d) : "l"(a), "l"(b), "l"(c));
    return d;
}
__device__ __forceinline__ ull mul2(ull a, ull b) {
    ull d;
    asm("fma.rn.f32x2 %0, %1, %2, %3;" : "=l"(d) : "l"(a), "l"(b), "l"(0ULL));
    return d;
}
__device__ __forceinline__ ull bc2(float w) {
    ull u;
    asm("mov.b64 %0, {%1, %1};" : "=l"(u) : "f"(w));
    return u;
}
__device__ __forceinline__ ull pk2(float x, float y) {
    ull u;
    asm("mov.b64 %0, {%1, %2};" : "=l"(u) : "f"(x), "f"(y));
    return u;
}
__device__ __forceinline__ float lo2(ull u) {
    float x; asm("{ .reg .f32 hi; mov.b64 {%0, hi}, %1; }" : "=f"(x) : "l"(u));
    return x;
}
__device__ __forceinline__ float hi2(ull u) {
    float y; asm("{ .reg .f32 lo; mov.b64 {lo, %0}, %1; }" : "=f"(y) : "l"(u));
    return y;
}
__device__ __forceinline__ ull neg2(ull a) { return a ^ 0x8000000080000000ULL; }
__device__ __forceinline__ ull add2(ull a, ull b) { return fma2(bc2(1.0f), a, b); }

__device__ double g_sum;
__device__ unsigned g_cnt;

__global__ __launch_bounds__(NTHREADS, 5)
void ssim_main(const float* __restrict__ img1, const float* __restrict__ img2,
               float* __restrict__ out, double inv_n, unsigned nblocks) {
    extern __shared__ float sm[];
    float* sI1 = sm;                               // IH * PITCH_I floats
    float* sI2 = sm + IH * PITCH_I;
    ull*   sCS = (ull*)(sm + 2 * IH * PITCH_I);    // 5 * TH * CS_PITCH float2
    __shared__ double sRed[NWARPS];

    const int tid = threadIdx.x;
    const int wrp = tid >> 5;
    const int lan = tid & 31;
    const int plane = blockIdx.z;
    const int ty0 = blockIdx.y * TH;
    const int tx0 = blockIdx.x * TW;
    const float* p1 = img1 + (size_t)plane * (IMG_H * IMG_W);
    const float* p2 = img2 + (size_t)plane * (IMG_H * IMG_W);

    // -------- phase 1: load halo'd tile, warp-row / lane-column mapping ----
    {
        const int gx0 = tx0 - HALO;
        for (int y = wrp; y < IH; y += NWARPS) {
            const int gy = ty0 - HALO + y;
            const bool yin = (unsigned)gy < (unsigned)IMG_H;
            const int gbase = gy * IMG_W + gx0;
            float* d1 = sI1 + y * PITCH_I;
            float* d2 = sI2 + y * PITCH_I;
#pragma unroll
            for (int c = 0; c < 3; c++) {
                int lx = lan + 32 * c;
                if (c < 2 || lx < IW) {
                    float a = 0.0f, b = 0.0f;
                    if (yin && (unsigned)(gx0 + lx) < (unsigned)IMG_W) {
                        a = p1[gbase + lx];
                        b = p2[gbase + lx];
                    }
                    d1[lx] = a;
                    d2[lx] = b;
                }
            }
        }
    }
    __syncthreads();

    // -------- phase 2: vertical conv, all 5 quantities per task ------------
    // 148 tasks = xh in [0,37) x strip s in [0,4) of 4 output rows.
    if (tid < 148) {
        const int xh = tid % 37;
        const int s  = tid / 37;
        const ull* pa = (const ull*)sI1 + (4 * s) * PITCH_IU + xh;
        const ull* pb = (const ull*)sI2 + (4 * s) * PITCH_IU + xh;
        ull acc[5][4];
#pragma unroll
        for (int q = 0; q < 5; q++)
#pragma unroll
            for (int k = 0; k < 4; k++) acc[q][k] = 0ULL;

#pragma unroll
        for (int j = 0; j < 14; j++) {
            ull a  = pa[j * PITCH_IU];
            ull b  = pb[j * PITCH_IU];
            ull aa = mul2(a, a);
            ull bb = mul2(b, b);
            ull ab = mul2(a, b);
#pragma unroll
            for (int k = 0; k < 4; k++) {
                if ((unsigned)(j - k) < 11u) {
                    ull wp = bc2(W[j - k]);
                    acc[0][k] = fma2(wp, a,  acc[0][k]);
                    acc[1][k] = fma2(wp, b,  acc[1][k]);
                    acc[2][k] = fma2(wp, aa, acc[2][k]);
                    acc[3][k] = fma2(wp, bb, acc[3][k]);
                    acc[4][k] = fma2(wp, ab, acc[4][k]);
                }
            }
        }
#pragma unroll
        for (int q = 0; q < 5; q++)
#pragma unroll
            for (int k = 0; k < 4; k++)
                sCS[(q * TH + 4 * s + k) * CS_PITCH + xh] = acc[q][k];
    }
    __syncthreads();

    // -------- phase 3: horizontal conv packed over x-pairs + SSIM ----------
    // 128 active threads: y = tid&15, xb = tid>>4 in [0,8): 4 packs = 8 px.
    float local = 0.0f;
    if (tid < 128) {
        const int y  = tid & 15;
        const int xb = tid >> 4;

        // hoisted packed weights (constant-indexed -> registers)
        ull Wp[11];
#pragma unroll
        for (int w = 0; w < 11; w++) Wp[w] = bc2(W[w]);

        ull m[5][4];
#pragma unroll
        for (int q = 0; q < 5; q++)
#pragma unroll
            for (int o = 0; o < 4; o++) m[q][o] = 0ULL;

#pragma unroll
        for (int q = 0; q < 5; q++) {
            const ull* cs = sCS + (q * TH + y) * CS_PITCH + 4 * xb;
            ull Pp = cs[0];
            m[q][0] = fma2(Wp[0], Pp, m[q][0]);          // e=0 aligned, o=0
#pragma unroll
            for (int i = 1; i < 9; i++) {
                ull Pi = cs[i];
                ull Se = pk2(hi2(Pp), lo2(Pi));          // shifted pair e=i-1
#pragma unroll
                for (int o = 0; o < 4; o++) {
                    int d = (i - 1) - o;                 // shifted tap 2d+1
                    if (d >= 0 && d <= 4)
                        m[q][o] = fma2(Wp[2 * d + 1], Se, m[q][o]);
                    int e = i - o;                       // aligned tap 2e
                    if (e >= 0 && e <= 5)
                        m[q][o] = fma2(Wp[2 * e], Pi, m[q][o]);
                }
                Pp = Pi;
            }
        }

        const ull C1p  = bc2(1e-4f);
        const ull C2p  = bc2(9e-4f);
        const ull TWOp = bc2(2.0f);
#pragma unroll
        for (int o = 0; o < 4; o++) {
            ull m1 = m[0][o], m2 = m[1][o];
            ull m1s = mul2(m1, m1);
            ull m2s = mul2(m2, m2);
            ull m12 = mul2(m1, m2);
            ull nm1 = neg2(m1);
            ull s1  = fma2(nm1, m1, m[2][o]);
            ull s2  = fma2(neg2(m2), m2, m[3][o]);
            ull s12 = fma2(nm1, m2, m[4][o]);
            ull numA = fma2(TWOp, m12, C1p);
            ull numB = fma2(TWOp, s12, C2p);
            ull denA = add2(m1s, add2(m2s, C1p));
            ull denB = add2(s1,  add2(s2,  C2p));
            ull num  = mul2(numA, numB);
            ull den  = mul2(denA, denB);
            local += __fdividef(lo2(num), lo2(den));
            local += __fdividef(hi2(num), hi2(den));
        }
    }

    // -------- reduction ----------------------------------------------------
    {
        unsigned mask = 0xffffffffu;
#pragma unroll
        for (int s = 16; s > 0; s >>= 1) local += __shfl_down_sync(mask, local, s);
        if (lan == 0) sRed[wrp] = (double)local;
    }
    __syncthreads();

    if (tid == 0) {
        double s = 0.0;
#pragma unroll
        for (int w = 0; w < NWARPS; w++) s += sRed[w];
        atomicAdd(&g_sum, s);
        __threadfence();
        unsigned done = atomicAdd(&g_cnt, 1);
        if (done == nblocks - 1) {
            double v = *((volatile double*)&g_sum);
            out[0] = (float)(v * inv_n);
            g_sum = 0.0;
            g_cnt = 0;
            __threadfence();
        }
    }
}

// ---------------------------------------------------------------------------

extern "C" void kernel_launch(void* const* d_in, const int* in_sizes, int n_in,
                              void* d_out, int out_size) {
    const float* img1 = (const float*)d_in[0];
    const float* img2 = (const float*)d_in[1];
    float* out = (float*)d_out;

    const int total  = in_sizes[0];                 // 16*3*512*512
    const int planes = total / (IMG_H * IMG_W);     // 48

    const int smem_bytes = 2 * IH * PITCH_I * (int)sizeof(float)
                         + 5 * TH * CS_PITCH * (int)sizeof(ull);  // 15808+23680=39488

    static bool attr_set = false;
    if (!attr_set) {
        cudaFuncSetAttribute(ssim_main, cudaFuncAttributeMaxDynamicSharedMemorySize,
                             smem_bytes);
        attr_set = true;
    }

    dim3 grid(IMG_W / TW, IMG_H / TH, planes);      // 8 x 32 x 48 = 12288
    unsigned nblocks = grid.x * grid.y * grid.z;
    ssim_main<<<grid, NTHREADS, smem_bytes>>>(img1, img2, out,
                                              1.0 / (double)total, nblocks);
}

// round 7
// speedup vs baseline: 2.0625x; 1.3145x over previous
#include <cuda_runtime.h>

// ---------------------------------------------------------------------------
// SSIM fused kernel, f32x2-packed, TW=128 / 288-thread variant, sm_100a.
// (16,3,512,512) fp32 pairs -> mean SSIM.
// R7: fixes R6's phase-1 chunk-2 guard (l < NXP, not l < NXP-64).
// ---------------------------------------------------------------------------

#define IMG_H 512
#define IMG_W 512
#define TW 128
#define TH 16
#define IW 140                // stored input width: cols 0..139 <-> gx tx0-6 .. tx0+133
#define IH 26                 // TH + 10
#define PITCH_I 142           // input smem pitch (floats, even)
#define PITCH_IU 71           // input smem pitch (float2)
#define NXP 70                // stored x-pairs per row
#define CS_PITCH 71           // colsum pitch (float2), odd -> conflict-free
#define NTHREADS 288
#define NWARPS 9

typedef unsigned long long ull;

// ---- compile-time Gaussian weights, double precision (match numpy) --------
constexpr double expser(double x) {
    double t = 1.0, s = 1.0;
    for (int k = 1; k < 100; k++) { t = t * x / (double)k; s += t; }
    return s;
}
constexpr double gk(int i) { double d = (double)(i - 5); return 1.0 / expser(d * d / 4.5); }
constexpr double GSUM = gk(0)+gk(1)+gk(2)+gk(3)+gk(4)+gk(5)+gk(6)+gk(7)+gk(8)+gk(9)+gk(10);
constexpr float WF(int i) { return (float)(gk(i) / GSUM); }
__device__ constexpr float W[11] = {WF(0),WF(1),WF(2),WF(3),WF(4),WF(5),
                                    WF(6),WF(7),WF(8),WF(9),WF(10)};

// ---- f32x2 packed helpers -------------------------------------------------
__device__ __forceinline__ ull fma2(ull a, ull b, ull c) {
    ull d;
    asm("fma.rn.f32x2 %0, %1, %2, %3;" : "=l"(d) : "l"(a), "l"(b), "l"(c));
    return d;
}
__device__ __forceinline__ ull mul2(ull a, ull b) {
    ull d;
    asm("mul.rn.f32x2 %0, %1, %2;" : "=l"(d) : "l"(a), "l"(b));
    return d;
}
__device__ __forceinline__ ull add2(ull a, ull b) {
    ull d;
    asm("add.rn.f32x2 %0, %1, %2;" : "=l"(d) : "l"(a), "l"(b));
    return d;
}
__device__ __forceinline__ ull bc2(float w) {
    ull u;
    asm("mov.b64 %0, {%1, %1};" : "=l"(u) : "f"(w));
    return u;
}
__device__ __forceinline__ ull pk2(float x, float y) {
    ull u;
    asm("mov.b64 %0, {%1, %2};" : "=l"(u) : "f"(x), "f"(y));
    return u;
}
__device__ __forceinline__ float lo2(ull u) {
    float x; asm("{ .reg .f32 hi; mov.b64 {%0, hi}, %1; }" : "=f"(x) : "l"(u));
    return x;
}
__device__ __forceinline__ float hi2(ull u) {
    float y; asm("{ .reg .f32 lo; mov.b64 {lo, %0}, %1; }" : "=f"(y) : "l"(u));
    return y;
}
__device__ __forceinline__ ull neg2(ull a) { return a ^ 0x8000000080000000ULL; }

__device__ double g_sum;
__device__ unsigned g_cnt;

__global__ __launch_bounds__(NTHREADS, 3)
void ssim_main(const float* __restrict__ img1, const float* __restrict__ img2,
               float* __restrict__ out, double inv_n, unsigned nblocks) {
    extern __shared__ float sm[];
    float* sI1 = sm;                               // IH * PITCH_I floats
    float* sI2 = sm + IH * PITCH_I;
    ull*   sCS = (ull*)(sm + 2 * IH * PITCH_I);    // 5 * TH * CS_PITCH float2
    __shared__ double sRed[NWARPS];

    const int tid = threadIdx.x;
    const int wrp = tid >> 5;
    const int lan = tid & 31;
    const int plane = blockIdx.z;
    const int ty0 = blockIdx.y * TH;
    const int tx0 = blockIdx.x * TW;
    const float* p1 = img1 + (size_t)plane * (IMG_H * IMG_W);
    const float* p2 = img2 + (size_t)plane * (IMG_H * IMG_W);

    // -------- phase 1: vectorized float2 halo load -------------------------
    // smem col 0 <-> gx0 = tx0 - 6 (even => 8B-aligned), 70 float2 per row.
    {
        const int gx0 = tx0 - 6;
        for (int y = wrp; y < IH; y += NWARPS) {
            const int gy = ty0 - 5 + y;
            const bool yin = (unsigned)gy < (unsigned)IMG_H;
            const float2* g1 = (const float2*)(p1 + gy * IMG_W + gx0);
            const float2* g2 = (const float2*)(p2 + gy * IMG_W + gx0);
            float2* d1 = (float2*)(sI1 + y * PITCH_I);
            float2* d2 = (float2*)(sI2 + y * PITCH_I);
#pragma unroll
            for (int c = 0; c < 3; c++) {
                int l = lan + 32 * c;
                if (c < 2 || l < NXP) {
                    int gxp = gx0 + 2 * l;
                    float2 a = make_float2(0.f, 0.f), b = a;
                    if (yin && (unsigned)gxp < (unsigned)IMG_W) {
                        a = g1[l];
                        b = g2[l];
                    }
                    d1[l] = a;
                    d2[l] = b;
                }
            }
        }
    }
    __syncthreads();

    // -------- phase 2: vertical conv, all 5 quantities per task ------------
    // 280 tasks = xpair u in [0,70) x strip s in [0,4) of 4 output rows.
    if (tid < NXP * 4) {
        const int u = tid % NXP;
        const int s = tid / NXP;
        const ull* pa = (const ull*)sI1 + (4 * s) * PITCH_IU + u;
        const ull* pb = (const ull*)sI2 + (4 * s) * PITCH_IU + u;
        ull acc[5][4];
#pragma unroll
        for (int q = 0; q < 5; q++)
#pragma unroll
            for (int k = 0; k < 4; k++) acc[q][k] = 0ULL;

#pragma unroll
        for (int j = 0; j < 14; j++) {
            ull a  = pa[j * PITCH_IU];
            ull b  = pb[j * PITCH_IU];
            ull aa = mul2(a, a);
            ull bb = mul2(b, b);
            ull ab = mul2(a, b);
#pragma unroll
            for (int k = 0; k < 4; k++) {
                if ((unsigned)(j - k) < 11u) {
                    ull wp = bc2(W[j - k]);
                    acc[0][k] = fma2(wp, a,  acc[0][k]);
                    acc[1][k] = fma2(wp, b,  acc[1][k]);
                    acc[2][k] = fma2(wp, aa, acc[2][k]);
                    acc[3][k] = fma2(wp, bb, acc[3][k]);
                    acc[4][k] = fma2(wp, ab, acc[4][k]);
                }
            }
        }
#pragma unroll
        for (int q = 0; q < 5; q++)
#pragma unroll
            for (int k = 0; k < 4; k++)
                sCS[(q * TH + 4 * s + k) * CS_PITCH + u] = acc[q][k];
    }
    __syncthreads();

    // -------- phase 3: horizontal conv packed over x-pairs + SSIM ----------
    // 256 active: y = tid&15, xb = tid>>4 in [0,16): 4 packs = 8 px.
    // Output pair (out[2m], out[2m+1]), m = 4xb+o, taps at smem cols px+1..px+11:
    //   even weight W[2e]:   S[o+e], e=0..5, S[u] = (hi P[u], lo P[u+1])
    //   odd  weight W[2t+1]: P[o+t+1], t=0..4
    float local = 0.0f;
    if (tid < 256) {
        const int y  = tid & 15;
        const int xb = tid >> 4;

        ull Wp[11];
#pragma unroll
        for (int w = 0; w < 11; w++) Wp[w] = bc2(W[w]);

        ull m[5][4];
#pragma unroll
        for (int q = 0; q < 5; q++)
#pragma unroll
            for (int o = 0; o < 4; o++) m[q][o] = 0ULL;

#pragma unroll
        for (int q = 0; q < 5; q++) {
            const ull* cs = sCS + (q * TH + y) * CS_PITCH + 4 * xb;
            ull Pp = cs[0];
#pragma unroll
            for (int i = 1; i < 10; i++) {
                ull Pi = cs[i];
                ull S = pk2(hi2(Pp), lo2(Pi));       // S[i-1]
#pragma unroll
                for (int o = 0; o < 4; o++) {
                    int t = (i - 1) - o;             // S[o+t], weight W[2t], t=0..5
                    if (t >= 0 && t <= 5)
                        m[q][o] = fma2(Wp[2 * t], S, m[q][o]);
                    int e = i - o - 1;               // P[o+e+1], weight W[2e+1], e=0..4
                    if (e >= 0 && e <= 4)
                        m[q][o] = fma2(Wp[2 * e + 1], Pi, m[q][o]);
                }
                Pp = Pi;
            }
        }

        const ull C1p  = bc2(1e-4f);
        const ull C2p  = bc2(9e-4f);
        const ull TWOp = bc2(2.0f);
#pragma unroll
        for (int o = 0; o < 4; o++) {
            ull m1 = m[0][o], m2 = m[1][o];
            ull m1s = mul2(m1, m1);
            ull m2s = mul2(m2, m2);
            ull m12 = mul2(m1, m2);
            ull nm1 = neg2(m1);
            ull s1  = fma2(nm1, m1, m[2][o]);
            ull s2  = fma2(neg2(m2), m2, m[3][o]);
            ull s12 = fma2(nm1, m2, m[4][o]);
            ull numA = fma2(TWOp, m12, C1p);
            ull numB = fma2(TWOp, s12, C2p);
            ull denA = add2(m1s, add2(m2s, C1p));
            ull denB = add2(s1,  add2(s2,  C2p));
            ull num  = mul2(numA, numB);
            ull den  = mul2(denA, denB);
            local += __fdividef(lo2(num), lo2(den));
            local += __fdividef(hi2(num), hi2(den));
        }
    }

    // -------- reduction ----------------------------------------------------
    {
        unsigned mask = 0xffffffffu;
#pragma unroll
        for (int s = 16; s > 0; s >>= 1) local += __shfl_down_sync(mask, local, s);
        if (lan == 0) sRed[wrp] = (double)local;
    }
    __syncthreads();

    if (tid == 0) {
        double s = 0.0;
#pragma unroll
        for (int w = 0; w < NWARPS; w++) s += sRed[w];
        atomicAdd(&g_sum, s);
        __threadfence();
        unsigned done = atomicAdd(&g_cnt, 1);
        if (done == nblocks - 1) {
            double v = *((volatile double*)&g_sum);
            out[0] = (float)(v * inv_n);
            g_sum = 0.0;
            g_cnt = 0;
            __threadfence();
        }
    }
}

// ---------------------------------------------------------------------------

extern "C" void kernel_launch(void* const* d_in, const int* in_sizes, int n_in,
                              void* d_out, int out_size) {
    const float* img1 = (const float*)d_in[0];
    const float* img2 = (const float*)d_in[1];
    float* out = (float*)d_out;

    const int total  = in_sizes[0];                 // 16*3*512*512
    const int planes = total / (IMG_H * IMG_W);     // 48

    const int smem_bytes = 2 * IH * PITCH_I * (int)sizeof(float)
                         + 5 * TH * CS_PITCH * (int)sizeof(ull);  // 29536+45440=74976

    static bool attr_set = false;
    if (!attr_set) {
        cudaFuncSetAttribute(ssim_main, cudaFuncAttributeMaxDynamicSharedMemorySize,
                             smem_bytes);
        attr_set = true;
    }

    dim3 grid(IMG_W / TW, IMG_H / TH, planes);      // 4 x 32 x 48 = 6144
    unsigned nblocks = grid.x * grid.y * grid.z;
    ssim_main<<<grid, NTHREADS, smem_bytes>>>(img1, img2, out,
                                              1.0 / (double)total, nblocks);
}